// round 17
// baseline (speedup 1.0000x reference)
#include <cuda_runtime.h>
#include <cstdint>

typedef unsigned int u32;

// LSTM B=65536, T=20, I=36, H=30. Gate order i,f,g,o.
// Output: out[B,T,H] ++ h_n[1,B,H] ++ c_n[1,B,H], fp32.
//
// R16 skeleton, ONE change: slab split into xs (pitch 40) + hs (pitch 34).
// hs pitch 34 makes the epilogue h-write STS fully bank-conflict-free
// (was 4-way with the unified pitch-72 slab). Same math, bit-identical.

#define NB   65536
#define NT   20
#define NIn  36
#define NH   30

#define BLOCK 128                 // 4 warps, 128 batches per CTA
#define GRID  (NB / 128)          // 512

#define XPITCH 40                 // x cols 0..35 + pad; 160B rows (16B aligned)
#define HPITCH 34                 // h 0..29 | bias(30)=1 | pad 31..33
#define XS_FLOATS (32 * XPITCH)   // 1280
#define HS_FLOATS (32 * HPITCH + 4)  // 1092 (2-float k8 over-read pad, 16B rounded)
#define NTILE  15                 // N = 120 = 15 x 8, n = hh*4 + gate

// smem layout (bytes)
#define OFF_BF16 0                         // fp16 hi-only k16: 4ch*15j*32*uint2 = 15360
#define OFF_B8   15360                     // k8 fp16 hi-only: 15j*32*u32 = 1920
#define OFF_XS   17280                     // 4 * 5120 = 20480
#define OFF_HS   (OFF_XS + 4 * XS_FLOATS * 4)   // 37760; 4 * 4368 = 17472
#define SMEM_BYTES (OFF_HS + 4 * HS_FLOATS * 4) // 55232

// ---- fp16 helpers ----
__device__ __forceinline__ u32 f16x2_rn(float even, float odd) {
    u32 d;
    asm("cvt.rn.f16x2.f32 %0, %1, %2;" : "=r"(d) : "f"(odd), "f"(even));
    return d;
}

// ---- MMA wrappers ----
__device__ __forceinline__ void mma_f16(float* d, u32 a0, u32 a1, u32 a2, u32 a3,
                                        u32 b0, u32 b1) {
    asm volatile(
        "mma.sync.aligned.m16n8k16.row.col.f32.f16.f16.f32 "
        "{%0,%1,%2,%3}, {%4,%5,%6,%7}, {%8,%9}, {%0,%1,%2,%3};"
        : "+f"(d[0]), "+f"(d[1]), "+f"(d[2]), "+f"(d[3])
        : "r"(a0), "r"(a1), "r"(a2), "r"(a3), "r"(b0), "r"(b1));
}
__device__ __forceinline__ void mma_k8_f16(float* d, u32 a0, u32 a1, u32 b0) {
    asm volatile(
        "mma.sync.aligned.m16n8k8.row.col.f32.f16.f16.f32 "
        "{%0,%1,%2,%3}, {%4,%5}, {%6}, {%0,%1,%2,%3};"
        : "+f"(d[0]), "+f"(d[1]), "+f"(d[2]), "+f"(d[3])
        : "r"(a0), "r"(a1), "r"(b0));
}

// ---- activations: MUFU.TANH based ----
__device__ __forceinline__ float tanh_ap(float v) {
    float y;
    asm("tanh.approx.f32 %0, %1;" : "=f"(y) : "f"(v));
    return y;
}
__device__ __forceinline__ float sigmoid_f(float v) {
    return fmaf(tanh_ap(0.5f * v), 0.5f, 0.5f);
}

__device__ __forceinline__ u32 s2u(const void* p) {
    u32 a;
    asm("{ .reg .u64 t; cvta.to.shared.u64 t, %1; cvt.u32.u64 %0, t; }"
        : "=r"(a) : "l"(p));
    return a;
}
#define CP16(dst, src) \
    asm volatile("cp.async.cg.shared.global [%0], [%1], 16;" :: "r"(dst), "l"(src))
#define CP_COMMIT() asm volatile("cp.async.commit_group;" ::: "memory")
#define CP_WAIT0()  asm volatile("cp.async.wait_group 0;" ::: "memory")

// concatenated weights: row n (gate-interleaved), col k in [0,72)
__device__ __forceinline__ float wcat(int n, int k,
                                      const float* W_ih, const float* W_hh,
                                      const float* b_ih, const float* b_hh) {
    int g = n & 3, hh = n >> 2;
    int row = g * NH + hh;
    if (k < 36) return W_ih[row * NIn + k];
    if (k < 66) return W_hh[row * NH + (k - 36)];
    if (k == 66) return b_ih[row] + b_hh[row];
    return 0.0f;
}

__global__ void __launch_bounds__(BLOCK, 2)
lstm_hmma_t17(const float* __restrict__ x,
              const float* __restrict__ W_ih,
              const float* __restrict__ W_hh,
              const float* __restrict__ b_ih,
              const float* __restrict__ b_hh,
              float* __restrict__ out) {
    extern __shared__ __align__(16) char smraw[];
    uint2* BsF = reinterpret_cast<uint2*>(smraw + OFF_BF16);   // k16 fp16 hi-only
    u32*   Bs8 = reinterpret_cast<u32*>(smraw + OFF_B8);       // k8 fp16 hi-only
    const int wid = threadIdx.x >> 5;
    float* xs = reinterpret_cast<float*>(smraw + OFF_XS) + wid * XS_FLOATS;
    float* hs = reinterpret_cast<float*>(smraw + OFF_HS) + wid * HS_FLOATS;

    const int tid  = threadIdx.x;
    const int lane = tid & 31;
    const int wB   = blockIdx.x * 128 + wid * 32;          // warp's first batch
    const u32 xs_u = s2u(xs);

    // ---- B tables (one-time) ----
    // fp16 hi-only k16 chunks: k = 0..63
    for (int idx = tid; idx < 4 * NTILE * 32; idx += BLOCK) {
        int ch  = idx / (NTILE * 32);
        int rem = idx - ch * NTILE * 32;
        int j   = rem >> 5, ln = rem & 31;
        int n   = j * 8 + (ln >> 2);
        int kb  = 16 * ch + 2 * (ln & 3);
        uint2 e;
        e.x = f16x2_rn(wcat(n, kb,     W_ih, W_hh, b_ih, b_hh),
                       wcat(n, kb + 1, W_ih, W_hh, b_ih, b_hh));
        e.y = f16x2_rn(wcat(n, kb + 8, W_ih, W_hh, b_ih, b_hh),
                       wcat(n, kb + 9, W_ih, W_hh, b_ih, b_hh));
        BsF[idx] = e;
    }
    // k8 chunk: k = 64..71 (h28, h29, bias col 66, zeros), fp16 hi-only
    for (int idx = tid; idx < NTILE * 32; idx += BLOCK) {
        int j = idx >> 5, ln = idx & 31;
        int n = j * 8 + (ln >> 2);
        int kb = 64 + 2 * (ln & 3);
        Bs8[idx] = f16x2_rn(wcat(n, kb,     W_ih, W_hh, b_ih, b_hh),
                            wcat(n, kb + 1, W_ih, W_hh, b_ih, b_hh));
    }

    // ---- per-warp slab init: zeros; hs bias col 30 = 1 ----
#pragma unroll
    for (int i = lane; i < XS_FLOATS / 4; i += 32)
        *reinterpret_cast<float4*>(xs + 4 * i) = make_float4(0, 0, 0, 0);
#pragma unroll
    for (int i = lane; i < HS_FLOATS / 4; i += 32)
        *reinterpret_cast<float4*>(hs + 4 * i) = make_float4(0, 0, 0, 0);
    __syncwarp();
    hs[lane * HPITCH + 30] = 1.0f;      // one row per lane
    __syncthreads();

    // ---- prefetch x(t=0) via cp.async (xs cols 0..35 exactly) ----
#pragma unroll
    for (int k = 0; k < 9; k++) {
        int i = lane + 32 * k;          // 32 rows * 9 quads
        int rr = i / 9, q = i - rr * 9;
        CP16(xs_u + (rr * XPITCH + 4 * q) * 4,
             x + (size_t)(wB + rr) * (NT * NIn) + 4 * q);
    }
    CP_COMMIT();

    const int r    = lane >> 2;               // frag row 0..7
    const bool ev  = (lane & 1) == 0;
    const int rowp = r + (ev ? 0 : 8);        // m0 cell row; m1 = rowp+16
    const int hsel = (lane >> 1) & 1;         // hh = 2j + hsel
    const int kofs = 2 * (lane & 3);

    // ch2 first-quad per-lane base/stride (k 32..39 straddles x|h boundary)
    const int   str2  = (kofs < 4) ? XPITCH : HPITCH;
    const float* bas2 = (kofs < 4) ? (xs + 32 + kofs) : (hs + (kofs - 4));

    float c0[NTILE], c1[NTILE];
#pragma unroll
    for (int j = 0; j < NTILE; j++) { c0[j] = 0.0f; c1[j] = 0.0f; }

    for (int t = 0; t < NT; t++) {
        CP_WAIT0();
        __syncwarp();                         // x(t) and h(t-1) visible

        float D[8 * NTILE];                   // m0: 0..59, m1: 60..119
#pragma unroll
        for (int i = 0; i < 8 * NTILE; i++) D[i] = 0.0f;

        // ---- ch0, ch1 (k 0..31, pure x): fp16 single-pass ----
#pragma unroll
        for (int ch = 0; ch < 2; ch++) {
            int kb = 16 * ch + kofs;
            u32 A[8];
            {
                float2 f;
                f = *reinterpret_cast<const float2*>(xs + r * XPITCH + kb);            A[0] = f16x2_rn(f.x, f.y);
                f = *reinterpret_cast<const float2*>(xs + (r + 8) * XPITCH + kb);      A[1] = f16x2_rn(f.x, f.y);
                f = *reinterpret_cast<const float2*>(xs + r * XPITCH + kb + 8);        A[2] = f16x2_rn(f.x, f.y);
                f = *reinterpret_cast<const float2*>(xs + (r + 8) * XPITCH + kb + 8);  A[3] = f16x2_rn(f.x, f.y);
                f = *reinterpret_cast<const float2*>(xs + (r + 16) * XPITCH + kb);     A[4] = f16x2_rn(f.x, f.y);
                f = *reinterpret_cast<const float2*>(xs + (r + 24) * XPITCH + kb);     A[5] = f16x2_rn(f.x, f.y);
                f = *reinterpret_cast<const float2*>(xs + (r + 16) * XPITCH + kb + 8); A[6] = f16x2_rn(f.x, f.y);
                f = *reinterpret_cast<const float2*>(xs + (r + 24) * XPITCH + kb + 8); A[7] = f16x2_rn(f.x, f.y);
            }
#pragma unroll
            for (int j = 0; j < NTILE; j++) {
                uint2 B = BsF[(ch * NTILE + j) * 32 + lane];
                mma_f16(D + 4 * j,      A[0], A[1], A[2], A[3], B.x, B.y);  // m0
                mma_f16(D + 60 + 4 * j, A[4], A[5], A[6], A[7], B.x, B.y);  // m1
            }
        }

        // ---- ch2 (k 32..47: x tail | h 0..11): fp16 single-pass ----
        {
            u32 A[8];
            {
                float2 f;
                f = *reinterpret_cast<const float2*>(bas2 + r * str2);          A[0] = f16x2_rn(f.x, f.y);
                f = *reinterpret_cast<const float2*>(bas2 + (r + 8) * str2);    A[1] = f16x2_rn(f.x, f.y);
                f = *reinterpret_cast<const float2*>(hs + r * HPITCH + 4 + kofs);        A[2] = f16x2_rn(f.x, f.y);
                f = *reinterpret_cast<const float2*>(hs + (r + 8) * HPITCH + 4 + kofs);  A[3] = f16x2_rn(f.x, f.y);
                f = *reinterpret_cast<const float2*>(bas2 + (r + 16) * str2);   A[4] = f16x2_rn(f.x, f.y);
                f = *reinterpret_cast<const float2*>(bas2 + (r + 24) * str2);   A[5] = f16x2_rn(f.x, f.y);
                f = *reinterpret_cast<const float2*>(hs + (r + 16) * HPITCH + 4 + kofs); A[6] = f16x2_rn(f.x, f.y);
                f = *reinterpret_cast<const float2*>(hs + (r + 24) * HPITCH + 4 + kofs); A[7] = f16x2_rn(f.x, f.y);
            }
#pragma unroll
            for (int j = 0; j < NTILE; j++) {
                uint2 B = BsF[(2 * NTILE + j) * 32 + lane];
                mma_f16(D + 4 * j,      A[0], A[1], A[2], A[3], B.x, B.y);  // m0
                mma_f16(D + 60 + 4 * j, A[4], A[5], A[6], A[7], B.x, B.y);  // m1
            }
        }

        // ---- xs reads done: prefetch x(t+1) early ----
        if (t < NT - 1) {
#pragma unroll
            for (int k = 0; k < 9; k++) {
                int i = lane + 32 * k;
                int rr = i / 9, q = i - rr * 9;
                CP16(xs_u + (rr * XPITCH + 4 * q) * 4,
                     x + (size_t)(wB + rr) * (NT * NIn) + (t + 1) * NIn + 4 * q);
            }
            CP_COMMIT();
        }

        // ---- ch3 (k 48..63: h 12..27): fp16 single-pass ----
        {
            int hb = 12 + kofs;
            u32 A[8];
            {
                float2 f;
                f = *reinterpret_cast<const float2*>(hs + r * HPITCH + hb);            A[0] = f16x2_rn(f.x, f.y);
                f = *reinterpret_cast<const float2*>(hs + (r + 8) * HPITCH + hb);      A[1] = f16x2_rn(f.x, f.y);
                f = *reinterpret_cast<const float2*>(hs + r * HPITCH + hb + 8);        A[2] = f16x2_rn(f.x, f.y);
                f = *reinterpret_cast<const float2*>(hs + (r + 8) * HPITCH + hb + 8);  A[3] = f16x2_rn(f.x, f.y);
                f = *reinterpret_cast<const float2*>(hs + (r + 16) * HPITCH + hb);     A[4] = f16x2_rn(f.x, f.y);
                f = *reinterpret_cast<const float2*>(hs + (r + 24) * HPITCH + hb);     A[5] = f16x2_rn(f.x, f.y);
                f = *reinterpret_cast<const float2*>(hs + (r + 16) * HPITCH + hb + 8); A[6] = f16x2_rn(f.x, f.y);
                f = *reinterpret_cast<const float2*>(hs + (r + 24) * HPITCH + hb + 8); A[7] = f16x2_rn(f.x, f.y);
            }
#pragma unroll
            for (int j = 0; j < NTILE; j++) {
                uint2 B = BsF[(3 * NTILE + j) * 32 + lane];
                mma_f16(D + 4 * j,      A[0], A[1], A[2], A[3], B.x, B.y);  // m0
                mma_f16(D + 60 + 4 * j, A[4], A[5], A[6], A[7], B.x, B.y);  // m1
            }
        }

        // ---- k8 chunk (k 64..71: h 28,29 | bias | pad): fp16 single-pass ----
        {
            int hb = 28 + kofs;   // kofs=6 reads cols 34,35 -> pad/next row; B=0 there
            u32 A8[4];
            {
                float2 f;
                f = *reinterpret_cast<const float2*>(hs + r * HPITCH + hb);        A8[0] = f16x2_rn(f.x, f.y);
                f = *reinterpret_cast<const float2*>(hs + (r + 8) * HPITCH + hb);  A8[1] = f16x2_rn(f.x, f.y);
                f = *reinterpret_cast<const float2*>(hs + (r + 16) * HPITCH + hb); A8[2] = f16x2_rn(f.x, f.y);
                f = *reinterpret_cast<const float2*>(hs + (r + 24) * HPITCH + hb); A8[3] = f16x2_rn(f.x, f.y);
            }
#pragma unroll
            for (int j = 0; j < NTILE; j++) {
                u32 B = Bs8[j * 32 + lane];
                mma_k8_f16(D + 4 * j,      A8[0], A8[1], B);   // m0
                mma_k8_f16(D + 60 + 4 * j, A8[2], A8[3], B);   // m1
            }
        }

        // ---- epilogue: 2 cells per lane per ntile; conflict-free h STS ----
#pragma unroll
        for (int j = 0; j < NTILE; j++) {
#pragma unroll
            for (int m = 0; m < 2; m++) {
                float* Dm = D + 60 * m + 4 * j;
                float d0 = Dm[0], d1 = Dm[1], d2 = Dm[2], d3 = Dm[3];
                float s0 = __shfl_xor_sync(0xffffffffu, ev ? d2 : d0, 1);
                float s1 = __shfl_xor_sync(0xffffffffu, ev ? d3 : d1, 1);
                float gi = ev ? d0 : s0;
                float gf = ev ? d1 : s1;
                float gg = ev ? s0 : d2;
                float go = ev ? s1 : d3;
                float it = sigmoid_f(gi), ft = sigmoid_f(gf);
                float gt = tanh_ap(gg),   ot = sigmoid_f(go);
                float* cr = m ? c1 : c0;
                float cn = fmaf(ft, cr[j], it * gt);
                cr[j] = cn;
                hs[(rowp + 16 * m) * HPITCH + (2 * j + hsel)] = ot * tanh_ap(cn);
            }
        }
        __syncwarp();

        // ---- out write: 32 rows x 30 from hs ----
#pragma unroll
        for (int k = 0; k < 30; k++) {
            int i = lane + 32 * k;                  // < 960
            int rr = i / 30, cc = i - rr * 30;
            out[(size_t)(wB + rr) * (NT * NH) + t * NH + cc] = hs[rr * HPITCH + cc];
        }
        __syncwarp();   // h reads done before next t's A-frag build
    }

    // ---- final states ----
    float* hN = out + (size_t)NB * NT * NH;
    float* cN = hN + (size_t)NB * NH;
#pragma unroll
    for (int k = 0; k < 30; k++) {
        int i = lane + 32 * k;
        int rr = i / 30, cc = i - rr * 30;
        hN[(size_t)(wB + rr) * NH + cc] = hs[rr * HPITCH + cc];
    }
    __syncwarp();
#pragma unroll
    for (int j = 0; j < NTILE; j++) {
        hs[rowp * HPITCH + (2 * j + hsel)]        = c0[j];
        hs[(rowp + 16) * HPITCH + (2 * j + hsel)] = c1[j];
    }
    __syncwarp();
#pragma unroll
    for (int k = 0; k < 30; k++) {
        int i = lane + 32 * k;
        int rr = i / 30, cc = i - rr * 30;
        cN[(size_t)(wB + rr) * NH + cc] = hs[rr * HPITCH + cc];
    }
}

extern "C" void kernel_launch(void* const* d_in, const int* in_sizes, int n_in,
                              void* d_out, int out_size) {
    const float* x    = (const float*)d_in[0];
    const float* W_ih = (const float*)d_in[1];
    const float* W_hh = (const float*)d_in[2];
    const float* b_ih = (const float*)d_in[3];
    const float* b_hh = (const float*)d_in[4];
    float* out = (float*)d_out;

    cudaFuncSetAttribute(lstm_hmma_t17,
                         cudaFuncAttributeMaxDynamicSharedMemorySize, SMEM_BYTES);
    lstm_hmma_t17<<<GRID, BLOCK, SMEM_BYTES>>>(x, W_ih, W_hh, b_ih, b_hh, out);
}